// round 13
// baseline (speedup 1.0000x reference)
#include <cuda_runtime.h>
#include <cuda_fp16.h>
#include <math.h>
#include <stdint.h>

#define HIDDEN 768
#define BATCH 32
#define SEQ 512
#define NCHUNK 128
#define LC 8
#define LN_EPS 1e-12f
#define MAXT 384
#define MAXROWS (BATCH * MAXT)   // 12288

// GEMM tiling
#define BM 64
#define BN 128
#define BK 16
#define NCH (HIDDEN / BK)   // 48

// 2-stage smem layout, row stride 48 B (16B-aligned, ldmatrix conflict-free):
//   per stage: [Ahi 3072][Alo 3072][Bhi 6144][Blo 6144] = 18432 B
#define STG_B    18432
#define SMEM_GEMM (2 * STG_B)   // 36864 -> 4 CTAs/SM = 147456 B

// ---- device scratch ----
__device__ float g_scores[BATCH * SEQ];
__device__ int   g_start[BATCH * NCHUNK];
__device__ int   g_len[BATCH * NCHUNK];
__device__ int   g_totalT;
__device__ float g_s0;
__device__ unsigned int g_maxu[BATCH * HIDDEN];
__device__ int   g_cnt[BATCH];
__device__ int   g_rowsrc[MAXROWS + 64];
__device__ int   g_rowinfo[MAXROWS + 64];
__device__ __half g_Xhi[MAXROWS * HIDDEN];
__device__ __half g_Xlo[MAXROWS * HIDDEN];
__device__ __half g_Whi[HIDDEN * HIDDEN];
__device__ __half g_Wlo[HIDDEN * HIDDEN];

__device__ __forceinline__ uint32_t smem_u32(const void* p) {
    uint32_t a;
    asm("{ .reg .u64 t; cvta.to.shared.u64 t, %1; cvt.u32.u64 %0, t; }" : "=r"(a) : "l"(p));
    return a;
}

__device__ __forceinline__ uint32_t h2_as_u32(__half2 h) {
    union { __half2 h; uint32_t u; } cvt;
    cvt.h = h;
    return cvt.u;
}

// monotonic float<->uint key
__device__ __forceinline__ unsigned int fkey(float f) {
    unsigned int b = __float_as_uint(f);
    return (b & 0x80000000u) ? ~b : (b | 0x80000000u);
}
__device__ __forceinline__ float funkey(unsigned int k) {
    unsigned int b = (k & 0x80000000u) ? (k ^ 0x80000000u) : ~k;
    return __uint_as_float(b);
}

#define LDSM_X4(r, addr) \
    asm volatile("ldmatrix.sync.aligned.m8n8.x4.shared.b16 {%0,%1,%2,%3}, [%4];" \
        : "=r"((r)[0]), "=r"((r)[1]), "=r"((r)[2]), "=r"((r)[3]) : "r"(addr))

#define MMA16816(d, a, bf) \
    asm volatile("mma.sync.aligned.m16n8k16.row.col.f32.f16.f16.f32 " \
        "{%0,%1,%2,%3}, {%4,%5,%6,%7}, {%8,%9}, {%0,%1,%2,%3};" \
        : "+f"((d)[0]), "+f"((d)[1]), "+f"((d)[2]), "+f"((d)[3]) \
        : "r"((a)[0]), "r"((a)[1]), "r"((a)[2]), "r"((a)[3]), \
          "r"((bf)[0]), "r"((bf)[1]))

#define CP_ASYNC16(dst, src) \
    asm volatile("cp.async.cg.shared.global [%0], [%1], 16;" :: "r"(dst), "l"(src))
#define CP_COMMIT() asm volatile("cp.async.commit_group;" ::: "memory")
#define CP_WAIT(n)  asm volatile("cp.async.wait_group %0;" :: "n"(n) : "memory")

__device__ __forceinline__ void split_pack(float4 v, uint2& hi, uint2& lo) {
    __half2 h01 = __floats2half2_rn(v.x, v.y);
    __half2 h23 = __floats2half2_rn(v.z, v.w);
    float2 f01 = __half22float2(h01);
    float2 f23 = __half22float2(h23);
    __half2 l01 = __floats2half2_rn(v.x - f01.x, v.y - f01.y);
    __half2 l23 = __floats2half2_rn(v.z - f23.x, v.w - f23.y);
    hi.x = h2_as_u32(h01); hi.y = h2_as_u32(h23);
    lo.x = h2_as_u32(l01); lo.y = h2_as_u32(l23);
}

// ============================================================
// Kernel 1: setup — fused X/W split-convert + prefix scan + packing maps
// ============================================================
__global__ void __launch_bounds__(256)
setup_kernel(const float* __restrict__ tokens, const float* __restrict__ W,
             const int* __restrict__ chunk_lens,
             const float* __restrict__ dense_b,
             const float* __restrict__ attn_bias,
             const float* __restrict__ query) {
    int blk = blockIdx.x;
    int tid = threadIdx.x;

    if (blk < 768) {
        int b = blk / 24;
        int rg = blk - b * 24;
        int row0 = rg * 16;
        __shared__ int wsum[8];
        __shared__ int sT;
        int v = (tid < NCHUNK) ? chunk_lens[b * NCHUNK + tid] : 0;
        #pragma unroll
        for (int off = 16; off > 0; off >>= 1)
            v += __shfl_xor_sync(0xffffffffu, v, off);
        if ((tid & 31) == 0) wsum[tid >> 5] = v;
        __syncthreads();
        if (tid == 0) {
            int t = wsum[0] + wsum[1] + wsum[2] + wsum[3];
            if (t > SEQ) t = SEQ;
            if (t < 0) t = 0;
            sT = t;
        }
        __syncthreads();
        if (row0 >= sT) return;
        const float4* src = (const float4*)(tokens + ((size_t)b * SEQ + row0) * HIDDEN);
        size_t dst0 = ((size_t)b * MAXT + row0) * HIDDEN;
        #pragma unroll
        for (int i = 0; i < 12; ++i) {
            int idx = tid + i * 256;
            float4 val = src[idx];
            uint2 hi, lo;
            split_pack(val, hi, lo);
            *(uint2*)&g_Xhi[dst0 + (size_t)idx * 4] = hi;
            *(uint2*)&g_Xlo[dst0 + (size_t)idx * 4] = lo;
        }
    } else if (blk < 816) {
        int row0 = (blk - 768) * 16;
        const float4* src = (const float4*)(W + (size_t)row0 * HIDDEN);
        size_t dst0 = (size_t)row0 * HIDDEN;
        #pragma unroll
        for (int i = 0; i < 12; ++i) {
            int idx = tid + i * 256;
            float4 val = src[idx];
            uint2 hi, lo;
            split_pack(val, hi, lo);
            *(uint2*)&g_Whi[dst0 + (size_t)idx * 4] = hi;
            *(uint2*)&g_Wlo[dst0 + (size_t)idx * 4] = lo;
        }
    } else {
        int b = blk - 816;
        int warp = tid >> 5;
        int lane = tid & 31;

        __shared__ int sstart;
        if (tid == 0) sstart = 0;
        __syncthreads();
        for (int j = warp; j < b; j += 8) {
            const int* lp = chunk_lens + j * NCHUNK;
            int s = lp[lane] + lp[lane + 32] + lp[lane + 64] + lp[lane + 96];
            #pragma unroll
            for (int off = 16; off > 0; off >>= 1)
                s += __shfl_xor_sync(0xffffffffu, s, off);
            if (lane == 0) {
                if (s > SEQ) s = SEQ;
                if (s < 0) s = 0;
                atomicAdd(&sstart, s);
            }
        }

        __shared__ int sc[NCHUNK];
        int len = 0;
        if (tid < NCHUNK) {
            len = chunk_lens[b * NCHUNK + tid];
            sc[tid] = len;
        }
        __syncthreads();
        for (int off = 1; off < NCHUNK; off <<= 1) {
            int v = (tid < NCHUNK && tid >= off) ? sc[tid - off] : 0;
            __syncthreads();
            if (tid < NCHUNK) sc[tid] += v;
            __syncthreads();
        }
        __shared__ int sT;
        if (tid < NCHUNK) {
            int incl = sc[tid];
            g_start[b * NCHUNK + tid] = incl - len;
            int le = len;
            if (le < 0) le = 0;
            if (le > LC) le = LC;
            g_len[b * NCHUNK + tid] = le;
            if (tid == NCHUNK - 1) {
                int T = incl;
                if (T > SEQ) T = SEQ;
                if (T < 0) T = 0;
                sT = T;
            }
        }
        __syncthreads();
        int gstart = sstart;
        int T = sT;

        for (int t = tid; t < T; t += 256) {
            g_rowsrc[gstart + t]  = b * MAXT + t;
            g_rowinfo[gstart + t] = (b << 16) | t;
        }
        if (b == BATCH - 1) {
            int tot = gstart + T;
            if (tid == 0) g_totalT = tot;
            for (int i = tid; i < 64; i += 256) {
                g_rowsrc[tot + i]  = 0;
                g_rowinfo[tot + i] = 0;
            }
        }

        for (int t = tid; t < SEQ; t += 256) g_scores[b * SEQ + t] = 0.0f;
        for (int d = tid; d < HIDDEN; d += 256) g_maxu[b * HIDDEN + d] = 0u;
        if (tid == 0) g_cnt[b] = 0;

        if (b == 0) {
            float acc = 0.0f;
            for (int e = tid; e < HIDDEN; e += 256)
                acc += query[e] * tanhf(dense_b[e] + attn_bias[e]);
            #pragma unroll
            for (int off = 16; off > 0; off >>= 1)
                acc += __shfl_xor_sync(0xffffffffu, acc, off);
            __shared__ float red[8];
            if ((tid & 31) == 0) red[tid >> 5] = acc;
            __syncthreads();
            if (tid == 0) {
                float s = 0.0f;
                #pragma unroll
                for (int w = 0; w < 8; ++w) s += red[w];
                g_s0 = s;
            }
        }
    }
}

// ============================================================
// Kernel 2: HMMA GEMM over globally-packed rows
// BK=16, 2-stage, 48B row stride, 4 CTAs/SM (single wave)
// grid = (6 n-tiles, 192 m-tiles), 256 threads (8 warps 2m x 4n)
// ============================================================
__global__ void __launch_bounds__(256, 4)
gemm_hmma_kernel(const float* __restrict__ dense_b,
                 const float* __restrict__ attn_bias,
                 const float* __restrict__ query) {
    int totalT = g_totalT;
    int row0 = blockIdx.y * BM;
    if (row0 >= totalT) return;
    int e0 = blockIdx.x * BN;

    extern __shared__ char smem[];
    uint32_t S = smem_u32(smem);
    __shared__ float qs[BN], bbs[BN];
    __shared__ int ssrc[BM];

    int tid = threadIdx.x;
    int wid = tid >> 5;
    int lane = tid & 31;
    int warp_m = wid & 1;
    int warp_n = wid >> 1;

    if (tid < BN) {
        int e = e0 + tid;
        qs[tid]  = query[e];
        bbs[tid] = dense_b[e] + attn_bias[e];
    }
    if (tid < BM) ssrc[tid] = g_rowsrc[row0 + tid];
    __syncthreads();   // ssrc ready before A loads

    // 768 16B chunks/stage, 3 per thread.
    // A: idx<256: h=idx>>7, j=idx&127, r=j>>1, c16=j&1 -> dst h*3072 + r*48 + c16*16
    // B: idx>=256: j2=idx-256, h=j2>>8, j=j2&255, r=j>>1, c16=j&1 -> 6144 + h*6144 + r*48 + c16*16
    #define LOAD_STAGE(st, k0) do { \
        uint32_t base_ = S + (st) * STG_B; \
        _Pragma("unroll") \
        for (int i = 0; i < 3; ++i) { \
            int idx = tid + i * 256; \
            if (idx < 256) { \
                int h = idx >> 7; \
                int j = idx & 127; \
                int r = j >> 1, c16 = j & 1; \
                const __half* src = (h ? g_Xlo : g_Xhi) \
                    + (size_t)ssrc[r] * HIDDEN + (k0) + c16 * 8; \
                CP_ASYNC16(base_ + h * 3072 + r * 48 + c16 * 16, src); \
            } else { \
                int j2 = idx - 256; \
                int h = j2 >> 8; \
                int j = j2 & 255; \
                int r = j >> 1, c16 = j & 1; \
                const __half* src = (h ? g_Wlo : g_Whi) \
                    + ((size_t)(e0 + r)) * HIDDEN + (k0) + c16 * 8; \
                CP_ASYNC16(base_ + 6144 + h * 6144 + r * 48 + c16 * 16, src); \
            } \
        } \
        CP_COMMIT(); \
    } while (0)

    float acc[2][4][4] = {};

    int aRow = warp_m * 32 + (lane & 15);
    int aCol = (lane >> 4) * 8;
    int bRowP = warp_n * 32 + ((lane >> 4) << 3) + (lane & 7);
    int bColP = ((lane >> 3) & 1) * 8;

    LOAD_STAGE(0, 0);

    for (int s = 0; s < NCH; ++s) {
        int st = s & 1;
        if (s + 1 < NCH) {
            LOAD_STAGE(st ^ 1, (s + 1) * BK);
            CP_WAIT(1);
        } else {
            CP_WAIT(0);
        }
        __syncthreads();

        uint32_t aB = S + st * STG_B;
        uint32_t bB = aB + 6144;

        uint32_t ahi[2][4], alo[2][4], bhi[2][4], blo[2][4];
        #pragma unroll
        for (int mt = 0; mt < 2; ++mt) {
            uint32_t ao = aB + (uint32_t)((aRow + mt * 16) * 48 + aCol * 2);
            LDSM_X4(ahi[mt], ao);
            LDSM_X4(alo[mt], ao + 3072);
        }
        #pragma unroll
        for (int p = 0; p < 2; ++p) {
            uint32_t bo = bB + (uint32_t)((bRowP + p * 16) * 48 + bColP * 2);
            LDSM_X4(bhi[p], bo);
            LDSM_X4(blo[p], bo + 6144);
        }
        #pragma unroll
        for (int mt = 0; mt < 2; ++mt)
            #pragma unroll
            for (int nt = 0; nt < 4; ++nt) {
                MMA16816(acc[mt][nt], ahi[mt], &bhi[nt >> 1][(nt & 1) * 2]);
                MMA16816(acc[mt][nt], ahi[mt], &blo[nt >> 1][(nt & 1) * 2]);
                MMA16816(acc[mt][nt], alo[mt], &bhi[nt >> 1][(nt & 1) * 2]);
            }
        __syncthreads();
    }

    float part[2][2] = {};
    #pragma unroll
    for (int mt = 0; mt < 2; ++mt)
        #pragma unroll
        for (int nt = 0; nt < 4; ++nt) {
            int nl = warp_n * 32 + nt * 8 + (lane & 3) * 2;
            float q0 = qs[nl], q1 = qs[nl + 1];
            float b0 = bbs[nl], b1 = bbs[nl + 1];
            part[mt][0] += q0 * tanhf(acc[mt][nt][0] + b0)
                         + q1 * tanhf(acc[mt][nt][1] + b1);
            part[mt][1] += q0 * tanhf(acc[mt][nt][2] + b0)
                         + q1 * tanhf(acc[mt][nt][3] + b1);
        }
    #pragma unroll
    for (int mt = 0; mt < 2; ++mt)
        #pragma unroll
        for (int i = 0; i < 2; ++i) {
            part[mt][i] += __shfl_xor_sync(0xffffffffu, part[mt][i], 1);
            part[mt][i] += __shfl_xor_sync(0xffffffffu, part[mt][i], 2);
        }
    if ((lane & 3) == 0) {
        #pragma unroll
        for (int mt = 0; mt < 2; ++mt)
            #pragma unroll
            for (int i = 0; i < 2; ++i) {
                int r = row0 + warp_m * 32 + mt * 16 + i * 8 + (lane >> 2);
                if (r < totalT) {
                    int info = g_rowinfo[r];
                    atomicAdd(&g_scores[(info >> 16) * SEQ + (info & 0xFFFF)], part[mt][i]);
                }
            }
    }
}

// ============================================================
// Kernel 3: softmax + weighted sum + LayerNorm + fused max +
//           last-block sentence decode (counter)
// grid = 2048 blocks, 128 threads (4 warps = 2 chunks/block)
// ============================================================
__global__ void __launch_bounds__(128)
chunk_embed_kernel(const float* __restrict__ tokens,
                   const float* __restrict__ ln_w,
                   const float* __restrict__ ln_b,
                   float* __restrict__ out_chunk,
                   float* __restrict__ out_sent) {
    int tid = threadIdx.x;
    int warp = tid >> 5;
    int lane = tid & 31;
    int bc = blockIdx.x * 2 + (warp >> 1);
    int half = warp & 1;
    int b = bc >> 7;
    int len = g_len[bc];
    int start = g_start[bc];
    float s0 = g_s0;

    float sc[LC];
    #pragma unroll
    for (int j = 0; j < LC; j++) {
        if (j < len) {
            int t = start + j;
            if (t > SEQ - 1) t = SEQ - 1;
            if (t < 0) t = 0;
            sc[j] = g_scores[b * SEQ + t];
        } else {
            sc[j] = s0;
        }
    }
    float m = sc[0];
    #pragma unroll
    for (int j = 1; j < LC; j++) m = fmaxf(m, sc[j]);
    float den = 0.0f;
    float w8[LC];
    #pragma unroll
    for (int j = 0; j < LC; j++) { w8[j] = expf(sc[j] - m); den += w8[j]; }
    float inv_den = 1.0f / den;

    float v[12];
    #pragma unroll
    for (int i = 0; i < 12; ++i) v[i] = 0.0f;
    int dbase = half * 384 + lane;
    #pragma unroll
    for (int j = 0; j < LC; j++) {
        if (j < len) {
            int t = start + j;
            if (t > SEQ - 1) t = SEQ - 1;
            if (t < 0) t = 0;
            float wj = w8[j] * inv_den;
            const float* row = tokens + ((size_t)b * SEQ + t) * HIDDEN + dbase;
            #pragma unroll
            for (int i = 0; i < 12; ++i)
                v[i] += wj * row[i * 32];
        }
    }

    __shared__ float ssum[4], ssq[4];
    float tot = 0.0f;
    #pragma unroll
    for (int i = 0; i < 12; ++i) tot += v[i];
    #pragma unroll
    for (int off = 16; off > 0; off >>= 1)
        tot += __shfl_xor_sync(0xffffffffu, tot, off);
    if (lane == 0) ssum[warp] = tot;
    __syncthreads();
    int wb = warp & ~1;
    float u = (ssum[wb] + ssum[wb + 1]) * (1.0f / HIDDEN);

    float sq = 0.0f;
    #pragma unroll
    for (int i = 0; i < 12; ++i) { v[i] -= u; sq += v[i] * v[i]; }
    #pragma unroll
    for (int off = 16; off > 0; off >>= 1)
        sq += __shfl_xor_sync(0xffffffffu, sq, off);
    if (lane == 0) ssq[warp] = sq;
    __syncthreads();
    float inv = rsqrtf((ssq[wb] + ssq[wb + 1]) * (1.0f / HIDDEN) + LN_EPS);

    float* outp = out_chunk + (size_t)bc * HIDDEN + dbase;
    unsigned int* mx = &g_maxu[b * HIDDEN + dbase];
    const float* lw = ln_w + dbase;
    const float* lb = ln_b + dbase;
    #pragma unroll
    for (int i = 0; i < 12; ++i) {
        float o = lw[i * 32] * (v[i] * inv) + lb[i * 32];
        outp[i * 32] = o;
        atomicMax(&mx[i * 32], fkey(o));
    }

    __threadfence();
    __syncthreads();
    __shared__ int sdone;
    if (tid == 0) {
        int c = atomicAdd(&g_cnt[b], 1);
        sdone = (c == 63);
    }
    __syncthreads();
    if (sdone) {
        __threadfence();
        #pragma unroll
        for (int i = 0; i < 6; ++i) {
            int d = tid + i * 128;
            out_sent[b * HIDDEN + d] = funkey(g_maxu[b * HIDDEN + d]);
        }
    }
}

// ============================================================
extern "C" void kernel_launch(void* const* d_in, const int* in_sizes, int n_in,
                              void* d_out, int out_size) {
    const float* tokens    = (const float*)d_in[0];
    const int*   chunk_lens= (const int*)d_in[1];
    const float* dense_w   = (const float*)d_in[2];
    const float* dense_b   = (const float*)d_in[3];
    const float* attn_bias = (const float*)d_in[4];
    const float* query     = (const float*)d_in[5];
    const float* ln_w      = (const float*)d_in[6];
    const float* ln_b      = (const float*)d_in[7];
    float* out = (float*)d_out;

    float* out_chunk = out;
    float* out_sent  = out + (size_t)BATCH * NCHUNK * HIDDEN;

    static bool attr_set = false;
    if (!attr_set) {
        cudaFuncSetAttribute(gemm_hmma_kernel,
                             cudaFuncAttributeMaxDynamicSharedMemorySize, SMEM_GEMM);
        attr_set = true;
    }

    setup_kernel<<<848, 256>>>(tokens, dense_w, chunk_lens, dense_b, attn_bias, query);

    dim3 gB(HIDDEN / BN, MAXROWS / BM);   // (6, 192), early exit on totalT
    gemm_hmma_kernel<<<gB, 256, SMEM_GEMM>>>(dense_b, attn_bias, query);

    chunk_embed_kernel<<<BATCH * NCHUNK / 2, 128>>>(tokens, ln_w, ln_b, out_chunk, out_sent);
}

// round 14
// speedup vs baseline: 1.4182x; 1.4182x over previous
#include <cuda_runtime.h>
#include <cuda_fp16.h>
#include <math.h>
#include <stdint.h>

#define HIDDEN 768
#define BATCH 32
#define SEQ 512
#define NCHUNK 128
#define LC 8
#define LN_EPS 1e-12f
#define MAXT 384
#define MAXROWS (BATCH * MAXT)   // 12288

// GEMM tiling
#define BM 128
#define BN 128
#define BK 32
#define NCH (HIDDEN / BK)   // 24

// 2-stage smem, row stride 80 B (16B-aligned, conflict-free, proven in R11):
//   per stage: [Ahi 10240][Alo 10240][Bhi 10240][Blo 10240] = 40960 B
#define STG_B    40960
#define SMEM_GEMM (2 * STG_B)   // 81920 -> 2 CTAs/SM = 163840 B

// ---- device scratch ----
__device__ float g_scores[BATCH * SEQ];
__device__ int   g_start[BATCH * NCHUNK];
__device__ int   g_len[BATCH * NCHUNK];
__device__ int   g_totalT;
__device__ float g_s0;
__device__ unsigned int g_maxu[BATCH * HIDDEN];
__device__ int   g_cnt[BATCH];
__device__ int   g_rowsrc[MAXROWS + 128];
__device__ int   g_rowinfo[MAXROWS + 128];
__device__ __half g_Xhi[MAXROWS * HIDDEN];
__device__ __half g_Xlo[MAXROWS * HIDDEN];
__device__ __half g_Whi[HIDDEN * HIDDEN];
__device__ __half g_Wlo[HIDDEN * HIDDEN];

__device__ __forceinline__ uint32_t smem_u32(const void* p) {
    uint32_t a;
    asm("{ .reg .u64 t; cvta.to.shared.u64 t, %1; cvt.u32.u64 %0, t; }" : "=r"(a) : "l"(p));
    return a;
}

__device__ __forceinline__ uint32_t h2_as_u32(__half2 h) {
    union { __half2 h; uint32_t u; } cvt;
    cvt.h = h;
    return cvt.u;
}

// monotonic float<->uint key
__device__ __forceinline__ unsigned int fkey(float f) {
    unsigned int b = __float_as_uint(f);
    return (b & 0x80000000u) ? ~b : (b | 0x80000000u);
}
__device__ __forceinline__ float funkey(unsigned int k) {
    unsigned int b = (k & 0x80000000u) ? (k ^ 0x80000000u) : ~k;
    return __uint_as_float(b);
}

#define LDSM_X4(r, addr) \
    asm volatile("ldmatrix.sync.aligned.m8n8.x4.shared.b16 {%0,%1,%2,%3}, [%4];" \
        : "=r"((r)[0]), "=r"((r)[1]), "=r"((r)[2]), "=r"((r)[3]) : "r"(addr))

#define MMA16816(d, a, bf) \
    asm volatile("mma.sync.aligned.m16n8k16.row.col.f32.f16.f16.f32 " \
        "{%0,%1,%2,%3}, {%4,%5,%6,%7}, {%8,%9}, {%0,%1,%2,%3};" \
        : "+f"((d)[0]), "+f"((d)[1]), "+f"((d)[2]), "+f"((d)[3]) \
        : "r"((a)[0]), "r"((a)[1]), "r"((a)[2]), "r"((a)[3]), \
          "r"((bf)[0]), "r"((bf)[1]))

#define CP_ASYNC16(dst, src) \
    asm volatile("cp.async.cg.shared.global [%0], [%1], 16;" :: "r"(dst), "l"(src))
#define CP_COMMIT() asm volatile("cp.async.commit_group;" ::: "memory")
#define CP_WAIT(n)  asm volatile("cp.async.wait_group %0;" :: "n"(n) : "memory")

__device__ __forceinline__ void split_pack(float4 v, uint2& hi, uint2& lo) {
    __half2 h01 = __floats2half2_rn(v.x, v.y);
    __half2 h23 = __floats2half2_rn(v.z, v.w);
    float2 f01 = __half22float2(h01);
    float2 f23 = __half22float2(h23);
    __half2 l01 = __floats2half2_rn(v.x - f01.x, v.y - f01.y);
    __half2 l23 = __floats2half2_rn(v.z - f23.x, v.w - f23.y);
    hi.x = h2_as_u32(h01); hi.y = h2_as_u32(h23);
    lo.x = h2_as_u32(l01); lo.y = h2_as_u32(l23);
}

// ============================================================
// Kernel 1: setup — fused X/W split-convert + prefix scan + packing maps
// ============================================================
__global__ void __launch_bounds__(256)
setup_kernel(const float* __restrict__ tokens, const float* __restrict__ W,
             const int* __restrict__ chunk_lens,
             const float* __restrict__ dense_b,
             const float* __restrict__ attn_bias,
             const float* __restrict__ query) {
    int blk = blockIdx.x;
    int tid = threadIdx.x;

    if (blk < 768) {
        int b = blk / 24;
        int rg = blk - b * 24;
        int row0 = rg * 16;
        __shared__ int wsum[8];
        __shared__ int sT;
        int v = (tid < NCHUNK) ? chunk_lens[b * NCHUNK + tid] : 0;
        #pragma unroll
        for (int off = 16; off > 0; off >>= 1)
            v += __shfl_xor_sync(0xffffffffu, v, off);
        if ((tid & 31) == 0) wsum[tid >> 5] = v;
        __syncthreads();
        if (tid == 0) {
            int t = wsum[0] + wsum[1] + wsum[2] + wsum[3];
            if (t > SEQ) t = SEQ;
            if (t < 0) t = 0;
            sT = t;
        }
        __syncthreads();
        if (row0 >= sT) return;
        const float4* src = (const float4*)(tokens + ((size_t)b * SEQ + row0) * HIDDEN);
        size_t dst0 = ((size_t)b * MAXT + row0) * HIDDEN;
        #pragma unroll
        for (int i = 0; i < 12; ++i) {
            int idx = tid + i * 256;
            float4 val = src[idx];
            uint2 hi, lo;
            split_pack(val, hi, lo);
            *(uint2*)&g_Xhi[dst0 + (size_t)idx * 4] = hi;
            *(uint2*)&g_Xlo[dst0 + (size_t)idx * 4] = lo;
        }
    } else if (blk < 816) {
        int row0 = (blk - 768) * 16;
        const float4* src = (const float4*)(W + (size_t)row0 * HIDDEN);
        size_t dst0 = (size_t)row0 * HIDDEN;
        #pragma unroll
        for (int i = 0; i < 12; ++i) {
            int idx = tid + i * 256;
            float4 val = src[idx];
            uint2 hi, lo;
            split_pack(val, hi, lo);
            *(uint2*)&g_Whi[dst0 + (size_t)idx * 4] = hi;
            *(uint2*)&g_Wlo[dst0 + (size_t)idx * 4] = lo;
        }
    } else {
        int b = blk - 816;
        int warp = tid >> 5;
        int lane = tid & 31;

        __shared__ int sstart;
        if (tid == 0) sstart = 0;
        __syncthreads();
        for (int j = warp; j < b; j += 8) {
            const int* lp = chunk_lens + j * NCHUNK;
            int s = lp[lane] + lp[lane + 32] + lp[lane + 64] + lp[lane + 96];
            #pragma unroll
            for (int off = 16; off > 0; off >>= 1)
                s += __shfl_xor_sync(0xffffffffu, s, off);
            if (lane == 0) {
                if (s > SEQ) s = SEQ;
                if (s < 0) s = 0;
                atomicAdd(&sstart, s);
            }
        }

        __shared__ int sc[NCHUNK];
        int len = 0;
        if (tid < NCHUNK) {
            len = chunk_lens[b * NCHUNK + tid];
            sc[tid] = len;
        }
        __syncthreads();
        for (int off = 1; off < NCHUNK; off <<= 1) {
            int v = (tid < NCHUNK && tid >= off) ? sc[tid - off] : 0;
            __syncthreads();
            if (tid < NCHUNK) sc[tid] += v;
            __syncthreads();
        }
        __shared__ int sT;
        if (tid < NCHUNK) {
            int incl = sc[tid];
            g_start[b * NCHUNK + tid] = incl - len;
            int le = len;
            if (le < 0) le = 0;
            if (le > LC) le = LC;
            g_len[b * NCHUNK + tid] = le;
            if (tid == NCHUNK - 1) {
                int T = incl;
                if (T > SEQ) T = SEQ;
                if (T < 0) T = 0;
                sT = T;
            }
        }
        __syncthreads();
        int gstart = sstart;
        int T = sT;

        for (int t = tid; t < T; t += 256) {
            g_rowsrc[gstart + t]  = b * MAXT + t;
            g_rowinfo[gstart + t] = (b << 16) | t;
        }
        if (b == BATCH - 1) {
            int tot = gstart + T;
            if (tid == 0) g_totalT = tot;
            for (int i = tid; i < 128; i += 256) {
                g_rowsrc[tot + i]  = 0;
                g_rowinfo[tot + i] = 0;
            }
        }

        for (int t = tid; t < SEQ; t += 256) g_scores[b * SEQ + t] = 0.0f;
        for (int d = tid; d < HIDDEN; d += 256) g_maxu[b * HIDDEN + d] = 0u;
        if (tid == 0) g_cnt[b] = 0;

        if (b == 0) {
            float acc = 0.0f;
            for (int e = tid; e < HIDDEN; e += 256)
                acc += query[e] * tanhf(dense_b[e] + attn_bias[e]);
            #pragma unroll
            for (int off = 16; off > 0; off >>= 1)
                acc += __shfl_xor_sync(0xffffffffu, acc, off);
            __shared__ float red[8];
            if ((tid & 31) == 0) red[tid >> 5] = acc;
            __syncthreads();
            if (tid == 0) {
                float s = 0.0f;
                #pragma unroll
                for (int w = 0; w < 8; ++w) s += red[w];
                g_s0 = s;
            }
        }
    }
}

// ============================================================
// Kernel 2: HMMA GEMM over globally-packed rows
// BM=128, BN=128, BK=32, 2-stage, 2 CTAs/SM — single wave (~294 CTAs / 296 slots)
// 256 threads = 8 warps, 2 m-warps x 4 n-warps; each warp: 64 rows x 32 cols
// ============================================================
__global__ void __launch_bounds__(256, 2)
gemm_hmma_kernel(const float* __restrict__ dense_b,
                 const float* __restrict__ attn_bias,
                 const float* __restrict__ query) {
    int totalT = g_totalT;
    int row0 = blockIdx.y * BM;
    if (row0 >= totalT) return;
    int e0 = blockIdx.x * BN;

    extern __shared__ char smem[];
    uint32_t S = smem_u32(smem);
    __shared__ float qs[BN], bbs[BN];
    __shared__ int ssrc[BM];

    int tid = threadIdx.x;
    int wid = tid >> 5;
    int lane = tid & 31;
    int warp_m = wid & 1;          // 2 m-warps: 64 rows each
    int warp_n = wid >> 1;         // 4 n-warps: 32 cols each

    if (tid < BN) {
        int e = e0 + tid;
        qs[tid]  = query[e];
        bbs[tid] = dense_b[e] + attn_bias[e];
    }
    if (tid < BM) ssrc[tid] = g_rowsrc[row0 + tid];
    __syncthreads();   // ssrc ready before A loads

    // 2048 16B chunks/stage, 8 per thread.
    // A (idx<1024): h=idx>>9, j=idx&511, r=j>>2, c16=j&3 -> h*10240 + r*80 + c16*16
    // B (idx>=1024): idx2=idx-1024, same mapping -> 20480 + h*10240 + r*80 + c16*16
    #define LOAD_STAGE(st, k0) do { \
        uint32_t base_ = S + (st) * STG_B; \
        _Pragma("unroll") \
        for (int i = 0; i < 8; ++i) { \
            int idx = tid + i * 256; \
            if (idx < 1024) { \
                int h = idx >> 9; \
                int j = idx & 511; \
                int r = j >> 2, c16 = j & 3; \
                const __half* src = (h ? g_Xlo : g_Xhi) \
                    + (size_t)ssrc[r] * HIDDEN + (k0) + c16 * 8; \
                CP_ASYNC16(base_ + h * 10240 + r * 80 + c16 * 16, src); \
            } else { \
                int j2 = idx - 1024; \
                int h = j2 >> 9; \
                int j = j2 & 511; \
                int r = j >> 2, c16 = j & 3; \
                const __half* src = (h ? g_Wlo : g_Whi) \
                    + ((size_t)(e0 + r)) * HIDDEN + (k0) + c16 * 8; \
                CP_ASYNC16(base_ + 20480 + h * 10240 + r * 80 + c16 * 16, src); \
            } \
        } \
        CP_COMMIT(); \
    } while (0)

    float acc[4][4][4] = {};

    int aRow = warp_m * 64 + (lane & 15);     // + mt*16, mt 0..3
    int aCol = (lane >> 4) * 8;
    int bRowP = warp_n * 32 + ((lane >> 4) << 3) + (lane & 7);
    int bColP = ((lane >> 3) & 1) * 8;

    LOAD_STAGE(0, 0);

    for (int s = 0; s < NCH; ++s) {
        int st = s & 1;
        if (s + 1 < NCH) {
            LOAD_STAGE(st ^ 1, (s + 1) * BK);
            CP_WAIT(1);
        } else {
            CP_WAIT(0);
        }
        __syncthreads();

        uint32_t aB = S + st * STG_B;
        uint32_t bB = aB + 20480;

        #pragma unroll
        for (int k16 = 0; k16 < 2; ++k16) {
            uint32_t ahi[4][4], alo[4][4], bhi[2][4], blo[2][4];
            #pragma unroll
            for (int mt = 0; mt < 4; ++mt) {
                uint32_t ao = aB + (uint32_t)((aRow + mt * 16) * 80 + (aCol + k16 * 16) * 2);
                LDSM_X4(ahi[mt], ao);
                LDSM_X4(alo[mt], ao + 10240);
            }
            #pragma unroll
            for (int p = 0; p < 2; ++p) {
                uint32_t bo = bB + (uint32_t)((bRowP + p * 16) * 80 + (bColP + k16 * 16) * 2);
                LDSM_X4(bhi[p], bo);
                LDSM_X4(blo[p], bo + 10240);
            }
            #pragma unroll
            for (int mt = 0; mt < 4; ++mt)
                #pragma unroll
                for (int nt = 0; nt < 4; ++nt) {
                    MMA16816(acc[mt][nt], ahi[mt], &bhi[nt >> 1][(nt & 1) * 2]);
                    MMA16816(acc[mt][nt], ahi[mt], &blo[nt >> 1][(nt & 1) * 2]);
                    MMA16816(acc[mt][nt], alo[mt], &bhi[nt >> 1][(nt & 1) * 2]);
                }
        }
        __syncthreads();
    }

    // epilogue: p[row] += sum_n q[n]*tanh(acc + bb[n]); quad reduce; atomic
    float part[4][2] = {};
    #pragma unroll
    for (int mt = 0; mt < 4; ++mt)
        #pragma unroll
        for (int nt = 0; nt < 4; ++nt) {
            int nl = warp_n * 32 + nt * 8 + (lane & 3) * 2;
            float q0 = qs[nl], q1 = qs[nl + 1];
            float b0 = bbs[nl], b1 = bbs[nl + 1];
            part[mt][0] += q0 * tanhf(acc[mt][nt][0] + b0)
                         + q1 * tanhf(acc[mt][nt][1] + b1);
            part[mt][1] += q0 * tanhf(acc[mt][nt][2] + b0)
                         + q1 * tanhf(acc[mt][nt][3] + b1);
        }
    #pragma unroll
    for (int mt = 0; mt < 4; ++mt)
        #pragma unroll
        for (int i = 0; i < 2; ++i) {
            part[mt][i] += __shfl_xor_sync(0xffffffffu, part[mt][i], 1);
            part[mt][i] += __shfl_xor_sync(0xffffffffu, part[mt][i], 2);
        }
    if ((lane & 3) == 0) {
        #pragma unroll
        for (int mt = 0; mt < 4; ++mt)
            #pragma unroll
            for (int i = 0; i < 2; ++i) {
                int r = row0 + warp_m * 64 + mt * 16 + i * 8 + (lane >> 2);
                if (r < totalT) {
                    int info = g_rowinfo[r];
                    atomicAdd(&g_scores[(info >> 16) * SEQ + (info & 0xFFFF)], part[mt][i]);
                }
            }
    }
}

// ============================================================
// Kernel 3: softmax + weighted sum + LayerNorm + fused max +
//           last-block sentence decode (counter)
// grid = 2048 blocks, 128 threads (4 warps = 2 chunks/block)
// ============================================================
__global__ void __launch_bounds__(128)
chunk_embed_kernel(const float* __restrict__ tokens,
                   const float* __restrict__ ln_w,
                   const float* __restrict__ ln_b,
                   float* __restrict__ out_chunk,
                   float* __restrict__ out_sent) {
    int tid = threadIdx.x;
    int warp = tid >> 5;
    int lane = tid & 31;
    int bc = blockIdx.x * 2 + (warp >> 1);
    int half = warp & 1;
    int b = bc >> 7;
    int len = g_len[bc];
    int start = g_start[bc];
    float s0 = g_s0;

    float sc[LC];
    #pragma unroll
    for (int j = 0; j < LC; j++) {
        if (j < len) {
            int t = start + j;
            if (t > SEQ - 1) t = SEQ - 1;
            if (t < 0) t = 0;
            sc[j] = g_scores[b * SEQ + t];
        } else {
            sc[j] = s0;
        }
    }
    float m = sc[0];
    #pragma unroll
    for (int j = 1; j < LC; j++) m = fmaxf(m, sc[j]);
    float den = 0.0f;
    float w8[LC];
    #pragma unroll
    for (int j = 0; j < LC; j++) { w8[j] = expf(sc[j] - m); den += w8[j]; }
    float inv_den = 1.0f / den;

    float v[12];
    #pragma unroll
    for (int i = 0; i < 12; ++i) v[i] = 0.0f;
    int dbase = half * 384 + lane;
    #pragma unroll
    for (int j = 0; j < LC; j++) {
        if (j < len) {
            int t = start + j;
            if (t > SEQ - 1) t = SEQ - 1;
            if (t < 0) t = 0;
            float wj = w8[j] * inv_den;
            const float* row = tokens + ((size_t)b * SEQ + t) * HIDDEN + dbase;
            #pragma unroll
            for (int i = 0; i < 12; ++i)
                v[i] += wj * row[i * 32];
        }
    }

    __shared__ float ssum[4], ssq[4];
    float tot = 0.0f;
    #pragma unroll
    for (int i = 0; i < 12; ++i) tot += v[i];
    #pragma unroll
    for (int off = 16; off > 0; off >>= 1)
        tot += __shfl_xor_sync(0xffffffffu, tot, off);
    if (lane == 0) ssum[warp] = tot;
    __syncthreads();
    int wb = warp & ~1;
    float u = (ssum[wb] + ssum[wb + 1]) * (1.0f / HIDDEN);

    float sq = 0.0f;
    #pragma unroll
    for (int i = 0; i < 12; ++i) { v[i] -= u; sq += v[i] * v[i]; }
    #pragma unroll
    for (int off = 16; off > 0; off >>= 1)
        sq += __shfl_xor_sync(0xffffffffu, sq, off);
    if (lane == 0) ssq[warp] = sq;
    __syncthreads();
    float inv = rsqrtf((ssq[wb] + ssq[wb + 1]) * (1.0f / HIDDEN) + LN_EPS);

    float* outp = out_chunk + (size_t)bc * HIDDEN + dbase;
    unsigned int* mx = &g_maxu[b * HIDDEN + dbase];
    const float* lw = ln_w + dbase;
    const float* lb = ln_b + dbase;
    #pragma unroll
    for (int i = 0; i < 12; ++i) {
        float o = lw[i * 32] * (v[i] * inv) + lb[i * 32];
        outp[i * 32] = o;
        atomicMax(&mx[i * 32], fkey(o));
    }

    __threadfence();
    __syncthreads();
    __shared__ int sdone;
    if (tid == 0) {
        int c = atomicAdd(&g_cnt[b], 1);
        sdone = (c == 63);
    }
    __syncthreads();
    if (sdone) {
        __threadfence();
        #pragma unroll
        for (int i = 0; i < 6; ++i) {
            int d = tid + i * 128;
            out_sent[b * HIDDEN + d] = funkey(g_maxu[b * HIDDEN + d]);
        }
    }
}

// ============================================================
extern "C" void kernel_launch(void* const* d_in, const int* in_sizes, int n_in,
                              void* d_out, int out_size) {
    const float* tokens    = (const float*)d_in[0];
    const int*   chunk_lens= (const int*)d_in[1];
    const float* dense_w   = (const float*)d_in[2];
    const float* dense_b   = (const float*)d_in[3];
    const float* attn_bias = (const float*)d_in[4];
    const float* query     = (const float*)d_in[5];
    const float* ln_w      = (const float*)d_in[6];
    const float* ln_b      = (const float*)d_in[7];
    float* out = (float*)d_out;

    float* out_chunk = out;
    float* out_sent  = out + (size_t)BATCH * NCHUNK * HIDDEN;

    static bool attr_set = false;
    if (!attr_set) {
        cudaFuncSetAttribute(gemm_hmma_kernel,
                             cudaFuncAttributeMaxDynamicSharedMemorySize, SMEM_GEMM);
        attr_set = true;
    }

    setup_kernel<<<848, 256>>>(tokens, dense_w, chunk_lens, dense_b, attn_bias, query);

    dim3 gB(HIDDEN / BN, MAXROWS / BM);   // (6, 96), early exit on totalT
    gemm_hmma_kernel<<<gB, 256, SMEM_GEMM>>>(dense_b, attn_bias, query);

    chunk_embed_kernel<<<BATCH * NCHUNK / 2, 128>>>(tokens, ln_w, ln_b, out_chunk, out_sent);
}

// round 16
// speedup vs baseline: 1.4362x; 1.0127x over previous
#include <cuda_runtime.h>
#include <cuda_fp16.h>
#include <math.h>
#include <stdint.h>

#define HIDDEN 768
#define BATCH 32
#define SEQ 512
#define NCHUNK 128
#define LC 8
#define LN_EPS 1e-12f
#define MAXT 384
#define MAXROWS (BATCH * MAXT)   // 12288

// GEMM tiling
#define BM 128
#define BN 128
#define BK 32
#define NCH (HIDDEN / BK)   // 24

// 2-stage smem, row stride 80 B: per stage [Ahi 10240][Alo 10240][Bhi 10240][Blo 10240]
#define STG_B    40960
#define SMEM_GEMM (2 * STG_B)   // 81920 -> 2 CTAs/SM

// setup grid
#define XBLKS 1536          // 48 blocks/batch, 8 rows each
#define WBLKS 48
#define SETUP_BLKS (XBLKS + WBLKS + BATCH)   // 1616

// ---- device scratch ----
__device__ float g_scores[BATCH * SEQ];
__device__ int   g_start[BATCH * NCHUNK];
__device__ int   g_len[BATCH * NCHUNK];
__device__ int   g_totalT;
__device__ float g_s0;
__device__ unsigned int g_maxu[BATCH * HIDDEN];
__device__ int   g_cnt[BATCH];
__device__ int   g_rowsrc[MAXROWS + 128];
__device__ int   g_rowinfo[MAXROWS + 128];
__device__ __half g_Xhi[MAXROWS * HIDDEN];
__device__ __half g_Xlo[MAXROWS * HIDDEN];
__device__ __half g_Whi[HIDDEN * HIDDEN];
__device__ __half g_Wlo[HIDDEN * HIDDEN];

__device__ __forceinline__ uint32_t smem_u32(const void* p) {
    uint32_t a;
    asm("{ .reg .u64 t; cvta.to.shared.u64 t, %1; cvt.u32.u64 %0, t; }" : "=r"(a) : "l"(p));
    return a;
}

__device__ __forceinline__ uint32_t h2_as_u32(__half2 h) {
    union { __half2 h; uint32_t u; } cvt;
    cvt.h = h;
    return cvt.u;
}

// monotonic float<->uint key
__device__ __forceinline__ unsigned int fkey(float f) {
    unsigned int b = __float_as_uint(f);
    return (b & 0x80000000u) ? ~b : (b | 0x80000000u);
}
__device__ __forceinline__ float funkey(unsigned int k) {
    unsigned int b = (k & 0x80000000u) ? (k ^ 0x80000000u) : ~k;
    return __uint_as_float(b);
}

#define LDSM_X4(r, addr) \
    asm volatile("ldmatrix.sync.aligned.m8n8.x4.shared.b16 {%0,%1,%2,%3}, [%4];" \
        : "=r"((r)[0]), "=r"((r)[1]), "=r"((r)[2]), "=r"((r)[3]) : "r"(addr))

#define MMA16816(d, a, bf) \
    asm volatile("mma.sync.aligned.m16n8k16.row.col.f32.f16.f16.f32 " \
        "{%0,%1,%2,%3}, {%4,%5,%6,%7}, {%8,%9}, {%0,%1,%2,%3};" \
        : "+f"((d)[0]), "+f"((d)[1]), "+f"((d)[2]), "+f"((d)[3]) \
        : "r"((a)[0]), "r"((a)[1]), "r"((a)[2]), "r"((a)[3]), \
          "r"((bf)[0]), "r"((bf)[1]))

#define CP_ASYNC16(dst, src) \
    asm volatile("cp.async.cg.shared.global [%0], [%1], 16;" :: "r"(dst), "l"(src))
#define CP_COMMIT() asm volatile("cp.async.commit_group;" ::: "memory")
#define CP_WAIT(n)  asm volatile("cp.async.wait_group %0;" :: "n"(n) : "memory")

__device__ __forceinline__ void split_pack(float4 v, uint2& hi, uint2& lo) {
    __half2 h01 = __floats2half2_rn(v.x, v.y);
    __half2 h23 = __floats2half2_rn(v.z, v.w);
    float2 f01 = __half22float2(h01);
    float2 f23 = __half22float2(h23);
    __half2 l01 = __floats2half2_rn(v.x - f01.x, v.y - f01.y);
    __half2 l23 = __floats2half2_rn(v.z - f23.x, v.w - f23.y);
    hi.x = h2_as_u32(h01); hi.y = h2_as_u32(h23);
    lo.x = h2_as_u32(l01); lo.y = h2_as_u32(l23);
}

// ============================================================
// Kernel 1: setup — fused X/W split-convert + prefix scan + packing maps
// grid = 1616 x 256:
//   blk 0..1535      : X convert (b = blk/48, 8 rows each)
//   blk 1536..1583   : W convert (16 rows each)
//   blk 1584..1615   : per-batch prep
// ============================================================
__global__ void __launch_bounds__(256)
setup_kernel(const float* __restrict__ tokens, const float* __restrict__ W,
             const int* __restrict__ chunk_lens,
             const float* __restrict__ dense_b,
             const float* __restrict__ attn_bias,
             const float* __restrict__ query) {
    int blk = blockIdx.x;
    int tid = threadIdx.x;

    if (blk < XBLKS) {
        int b = blk / 48;
        int rg = blk - b * 48;
        int row0 = rg * 8;
        __shared__ int wsum[8];
        __shared__ int sT;
        int v = (tid < NCHUNK) ? chunk_lens[b * NCHUNK + tid] : 0;
        #pragma unroll
        for (int off = 16; off > 0; off >>= 1)
            v += __shfl_xor_sync(0xffffffffu, v, off);
        if ((tid & 31) == 0) wsum[tid >> 5] = v;
        __syncthreads();
        if (tid == 0) {
            int t = wsum[0] + wsum[1] + wsum[2] + wsum[3];
            if (t > SEQ) t = SEQ;
            if (t < 0) t = 0;
            sT = t;
        }
        __syncthreads();
        if (row0 >= sT) return;
        const float4* src = (const float4*)(tokens + ((size_t)b * SEQ + row0) * HIDDEN);
        size_t dst0 = ((size_t)b * MAXT + row0) * HIDDEN;
        #pragma unroll
        for (int i = 0; i < 6; ++i) {
            int idx = tid + i * 256;     // 8 rows * 192 f4 = 1536
            float4 val = src[idx];
            uint2 hi, lo;
            split_pack(val, hi, lo);
            *(uint2*)&g_Xhi[dst0 + (size_t)idx * 4] = hi;
            *(uint2*)&g_Xlo[dst0 + (size_t)idx * 4] = lo;
        }
    } else if (blk < XBLKS + WBLKS) {
        int row0 = (blk - XBLKS) * 16;
        const float4* src = (const float4*)(W + (size_t)row0 * HIDDEN);
        size_t dst0 = (size_t)row0 * HIDDEN;
        #pragma unroll
        for (int i = 0; i < 12; ++i) {
            int idx = tid + i * 256;
            float4 val = src[idx];
            uint2 hi, lo;
            split_pack(val, hi, lo);
            *(uint2*)&g_Whi[dst0 + (size_t)idx * 4] = hi;
            *(uint2*)&g_Wlo[dst0 + (size_t)idx * 4] = lo;
        }
    } else {
        int b = blk - (XBLKS + WBLKS);
        int warp = tid >> 5;
        int lane = tid & 31;

        __shared__ int sstart;
        if (tid == 0) sstart = 0;
        __syncthreads();
        for (int j = warp; j < b; j += 8) {
            const int* lp = chunk_lens + j * NCHUNK;
            int s = lp[lane] + lp[lane + 32] + lp[lane + 64] + lp[lane + 96];
            #pragma unroll
            for (int off = 16; off > 0; off >>= 1)
                s += __shfl_xor_sync(0xffffffffu, s, off);
            if (lane == 0) {
                if (s > SEQ) s = SEQ;
                if (s < 0) s = 0;
                atomicAdd(&sstart, s);
            }
        }

        __shared__ int sc[NCHUNK];
        int len = 0;
        if (tid < NCHUNK) {
            len = chunk_lens[b * NCHUNK + tid];
            sc[tid] = len;
        }
        __syncthreads();
        for (int off = 1; off < NCHUNK; off <<= 1) {
            int v = (tid < NCHUNK && tid >= off) ? sc[tid - off] : 0;
            __syncthreads();
            if (tid < NCHUNK) sc[tid] += v;
            __syncthreads();
        }
        __shared__ int sT;
        if (tid < NCHUNK) {
            int incl = sc[tid];
            g_start[b * NCHUNK + tid] = incl - len;
            int le = len;
            if (le < 0) le = 0;
            if (le > LC) le = LC;
            g_len[b * NCHUNK + tid] = le;
            if (tid == NCHUNK - 1) {
                int T = incl;
                if (T > SEQ) T = SEQ;
                if (T < 0) T = 0;
                sT = T;
            }
        }
        __syncthreads();
        int gstart = sstart;
        int T = sT;

        for (int t = tid; t < T; t += 256) {
            g_rowsrc[gstart + t]  = b * MAXT + t;
            g_rowinfo[gstart + t] = (b << 16) | t;
        }
        if (b == BATCH - 1) {
            int tot = gstart + T;
            if (tid == 0) g_totalT = tot;
            for (int i = tid; i < 128; i += 256) {
                g_rowsrc[tot + i]  = 0;
                g_rowinfo[tot + i] = 0;
            }
        }

        for (int t = tid; t < SEQ; t += 256) g_scores[b * SEQ + t] = 0.0f;
        for (int d = tid; d < HIDDEN; d += 256) g_maxu[b * HIDDEN + d] = 0u;
        if (tid == 0) g_cnt[b] = 0;

        if (b == 0) {
            float acc = 0.0f;
            for (int e = tid; e < HIDDEN; e += 256)
                acc += query[e] * tanhf(dense_b[e] + attn_bias[e]);
            #pragma unroll
            for (int off = 16; off > 0; off >>= 1)
                acc += __shfl_xor_sync(0xffffffffu, acc, off);
            __shared__ float red[8];
            if ((tid & 31) == 0) red[tid >> 5] = acc;
            __syncthreads();
            if (tid == 0) {
                float s = 0.0f;
                #pragma unroll
                for (int w = 0; w < 8; ++w) s += red[w];
                g_s0 = s;
            }
        }
    }
}

// ============================================================
// Kernel 2: HMMA GEMM over globally-packed rows (identical to R14)
// ============================================================
__global__ void __launch_bounds__(256, 2)
gemm_hmma_kernel(const float* __restrict__ dense_b,
                 const float* __restrict__ attn_bias,
                 const float* __restrict__ query) {
    int totalT = g_totalT;
    int row0 = blockIdx.y * BM;
    if (row0 >= totalT) return;
    int e0 = blockIdx.x * BN;

    extern __shared__ char smem[];
    uint32_t S = smem_u32(smem);
    __shared__ float qs[BN], bbs[BN];
    __shared__ int ssrc[BM];

    int tid = threadIdx.x;
    int wid = tid >> 5;
    int lane = tid & 31;
    int warp_m = wid & 1;
    int warp_n = wid >> 1;

    if (tid < BN) {
        int e = e0 + tid;
        qs[tid]  = query[e];
        bbs[tid] = dense_b[e] + attn_bias[e];
    }
    if (tid < BM) ssrc[tid] = g_rowsrc[row0 + tid];
    __syncthreads();

    #define LOAD_STAGE(st, k0) do { \
        uint32_t base_ = S + (st) * STG_B; \
        _Pragma("unroll") \
        for (int i = 0; i < 8; ++i) { \
            int idx = tid + i * 256; \
            if (idx < 1024) { \
                int h = idx >> 9; \
                int j = idx & 511; \
                int r = j >> 2, c16 = j & 3; \
                const __half* src = (h ? g_Xlo : g_Xhi) \
                    + (size_t)ssrc[r] * HIDDEN + (k0) + c16 * 8; \
                CP_ASYNC16(base_ + h * 10240 + r * 80 + c16 * 16, src); \
            } else { \
                int j2 = idx - 1024; \
                int h = j2 >> 9; \
                int j = j2 & 511; \
                int r = j >> 2, c16 = j & 3; \
                const __half* src = (h ? g_Wlo : g_Whi) \
                    + ((size_t)(e0 + r)) * HIDDEN + (k0) + c16 * 8; \
                CP_ASYNC16(base_ + 20480 + h * 10240 + r * 80 + c16 * 16, src); \
            } \
        } \
        CP_COMMIT(); \
    } while (0)

    float acc[4][4][4] = {};

    int aRow = warp_m * 64 + (lane & 15);
    int aCol = (lane >> 4) * 8;
    int bRowP = warp_n * 32 + ((lane >> 4) << 3) + (lane & 7);
    int bColP = ((lane >> 3) & 1) * 8;

    LOAD_STAGE(0, 0);

    for (int s = 0; s < NCH; ++s) {
        int st = s & 1;
        if (s + 1 < NCH) {
            LOAD_STAGE(st ^ 1, (s + 1) * BK);
            CP_WAIT(1);
        } else {
            CP_WAIT(0);
        }
        __syncthreads();

        uint32_t aB = S + st * STG_B;
        uint32_t bB = aB + 20480;

        #pragma unroll
        for (int k16 = 0; k16 < 2; ++k16) {
            uint32_t ahi[4][4], alo[4][4], bhi[2][4], blo[2][4];
            #pragma unroll
            for (int mt = 0; mt < 4; ++mt) {
                uint32_t ao = aB + (uint32_t)((aRow + mt * 16) * 80 + (aCol + k16 * 16) * 2);
                LDSM_X4(ahi[mt], ao);
                LDSM_X4(alo[mt], ao + 10240);
            }
            #pragma unroll
            for (int p = 0; p < 2; ++p) {
                uint32_t bo = bB + (uint32_t)((bRowP + p * 16) * 80 + (bColP + k16 * 16) * 2);
                LDSM_X4(bhi[p], bo);
                LDSM_X4(blo[p], bo + 10240);
            }
            #pragma unroll
            for (int mt = 0; mt < 4; ++mt)
                #pragma unroll
                for (int nt = 0; nt < 4; ++nt) {
                    MMA16816(acc[mt][nt], ahi[mt], &bhi[nt >> 1][(nt & 1) * 2]);
                    MMA16816(acc[mt][nt], ahi[mt], &blo[nt >> 1][(nt & 1) * 2]);
                    MMA16816(acc[mt][nt], alo[mt], &bhi[nt >> 1][(nt & 1) * 2]);
                }
        }
        __syncthreads();
    }

    float part[4][2] = {};
    #pragma unroll
    for (int mt = 0; mt < 4; ++mt)
        #pragma unroll
        for (int nt = 0; nt < 4; ++nt) {
            int nl = warp_n * 32 + nt * 8 + (lane & 3) * 2;
            float q0 = qs[nl], q1 = qs[nl + 1];
            float b0 = bbs[nl], b1 = bbs[nl + 1];
            part[mt][0] += q0 * tanhf(acc[mt][nt][0] + b0)
                         + q1 * tanhf(acc[mt][nt][1] + b1);
            part[mt][1] += q0 * tanhf(acc[mt][nt][2] + b0)
                         + q1 * tanhf(acc[mt][nt][3] + b1);
        }
    #pragma unroll
    for (int mt = 0; mt < 4; ++mt)
        #pragma unroll
        for (int i = 0; i < 2; ++i) {
            part[mt][i] += __shfl_xor_sync(0xffffffffu, part[mt][i], 1);
            part[mt][i] += __shfl_xor_sync(0xffffffffu, part[mt][i], 2);
        }
    if ((lane & 3) == 0) {
        #pragma unroll
        for (int mt = 0; mt < 4; ++mt)
            #pragma unroll
            for (int i = 0; i < 2; ++i) {
                int r = row0 + warp_m * 64 + mt * 16 + i * 8 + (lane >> 2);
                if (r < totalT) {
                    int info = g_rowinfo[r];
                    atomicAdd(&g_scores[(info >> 16) * SEQ + (info & 0xFFFF)], part[mt][i]);
                }
            }
    }
}

// ============================================================
// Kernel 3: softmax + weighted sum + LayerNorm + fused max +
//           last-block sentence decode (unified path — uniform barriers)
// grid = 2048 blocks, 128 threads (4 warps = 2 chunks/block)
// ============================================================
__global__ void __launch_bounds__(128)
chunk_embed_kernel(const float* __restrict__ tokens,
                   const float* __restrict__ ln_w,
                   const float* __restrict__ ln_b,
                   float* __restrict__ out_chunk,
                   float* __restrict__ out_sent) {
    int tid = threadIdx.x;
    int warp = tid >> 5;
    int lane = tid & 31;
    int bc = blockIdx.x * 2 + (warp >> 1);
    int half = warp & 1;
    int b = bc >> 7;
    int len = g_len[bc];
    int start = g_start[bc];
    float s0 = g_s0;

    float sc[LC];
    #pragma unroll
    for (int j = 0; j < LC; j++) {
        if (j < len) {
            int t = start + j;
            if (t > SEQ - 1) t = SEQ - 1;
            if (t < 0) t = 0;
            sc[j] = g_scores[b * SEQ + t];
        } else {
            sc[j] = s0;
        }
    }
    float m = sc[0];
    #pragma unroll
    for (int j = 1; j < LC; j++) m = fmaxf(m, sc[j]);
    float den = 0.0f;
    float w8[LC];
    #pragma unroll
    for (int j = 0; j < LC; j++) { w8[j] = expf(sc[j] - m); den += w8[j]; }
    float inv_den = 1.0f / den;

    float v[12];
    #pragma unroll
    for (int i = 0; i < 12; ++i) v[i] = 0.0f;
    int dbase = half * 384 + lane;
    #pragma unroll
    for (int j = 0; j < LC; j++) {
        if (j < len) {
            int t = start + j;
            if (t > SEQ - 1) t = SEQ - 1;
            if (t < 0) t = 0;
            float wj = w8[j] * inv_den;
            const float* row = tokens + ((size_t)b * SEQ + t) * HIDDEN + dbase;
            #pragma unroll
            for (int i = 0; i < 12; ++i)
                v[i] += wj * row[i * 32];
        }
    }

    __shared__ float ssum[4], ssq[4];
    float tot = 0.0f;
    #pragma unroll
    for (int i = 0; i < 12; ++i) tot += v[i];
    #pragma unroll
    for (int off = 16; off > 0; off >>= 1)
        tot += __shfl_xor_sync(0xffffffffu, tot, off);
    if (lane == 0) ssum[warp] = tot;
    __syncthreads();
    int wb = warp & ~1;
    float u = (ssum[wb] + ssum[wb + 1]) * (1.0f / HIDDEN);

    float sq = 0.0f;
    #pragma unroll
    for (int i = 0; i < 12; ++i) { v[i] -= u; sq += v[i] * v[i]; }
    #pragma unroll
    for (int off = 16; off > 0; off >>= 1)
        sq += __shfl_xor_sync(0xffffffffu, sq, off);
    if (lane == 0) ssq[warp] = sq;
    __syncthreads();
    float inv = rsqrtf((ssq[wb] + ssq[wb + 1]) * (1.0f / HIDDEN) + LN_EPS);

    float* outp = out_chunk + (size_t)bc * HIDDEN + dbase;
    unsigned int* mx = &g_maxu[b * HIDDEN + dbase];
    const float* lw = ln_w + dbase;
    const float* lb = ln_b + dbase;
    #pragma unroll
    for (int i = 0; i < 12; ++i) {
        float o = lw[i * 32] * (v[i] * inv) + lb[i * 32];
        outp[i * 32] = o;
        atomicMax(&mx[i * 32], fkey(o));
    }

    __threadfence();
    __syncthreads();
    __shared__ int sdone;
    if (tid == 0) {
        int c = atomicAdd(&g_cnt[b], 1);
        sdone = (c == 63);
    }
    __syncthreads();
    if (sdone) {
        __threadfence();
        #pragma unroll
        for (int i = 0; i < 6; ++i) {
            int d = tid + i * 128;
            out_sent[b * HIDDEN + d] = funkey(g_maxu[b * HIDDEN + d]);
        }
    }
}

// ============================================================
extern "C" void kernel_launch(void* const* d_in, const int* in_sizes, int n_in,
                              void* d_out, int out_size) {
    const float* tokens    = (const float*)d_in[0];
    const int*   chunk_lens= (const int*)d_in[1];
    const float* dense_w   = (const float*)d_in[2];
    const float* dense_b   = (const float*)d_in[3];
    const float* attn_bias = (const float*)d_in[4];
    const float* query     = (const float*)d_in[5];
    const float* ln_w      = (const float*)d_in[6];
    const float* ln_b      = (const float*)d_in[7];
    float* out = (float*)d_out;

    float* out_chunk = out;
    float* out_sent  = out + (size_t)BATCH * NCHUNK * HIDDEN;

    static bool attr_set = false;
    if (!attr_set) {
        cudaFuncSetAttribute(gemm_hmma_kernel,
                             cudaFuncAttributeMaxDynamicSharedMemorySize, SMEM_GEMM);
        attr_set = true;
    }

    setup_kernel<<<SETUP_BLKS, 256>>>(tokens, dense_w, chunk_lens, dense_b, attn_bias, query);

    dim3 gB(HIDDEN / BN, MAXROWS / BM);   // (6, 96), early exit on totalT
    gemm_hmma_kernel<<<gB, 256, SMEM_GEMM>>>(dense_b, attn_bias, query);

    chunk_embed_kernel<<<BATCH * NCHUNK / 2, 128>>>(tokens, ln_w, ln_b, out_chunk, out_sent);
}